// round 14
// baseline (speedup 1.0000x reference)
#include <cuda_runtime.h>
#include <cuda_fp16.h>
#include <cstdint>

// out = 0.9*p + 0.1 * softmax(-4 p p^T) p    N=16384, D=64, fp32
// FA2 flash attention, single-pass f16 QK/PV. TM=128: 8 warps, each 32 rows x
// 32 keys (key-split halves), 2 m-blocks share every B fragment (halved LDSM).
// Software-pipelined: QK(t+1); PV(t) || softmax(t+1). 3-deep K ring.

#define D_DIM 64
#define TM    128
#define TN    64
#define NTH   256
#define PN    (16384*64)
#define QSCALE 5.770780163555854f   // 4*log2(e)

__device__ __half g_qh[PN];   // fp16(QSCALE*p)
__device__ __half g_ph[PN];   // fp16(p)  (K / V)

__device__ __forceinline__ uint32_t smem_u32(const void* p) {
    uint32_t a;
    asm("{ .reg .u64 t; cvta.to.shared.u64 t, %1; cvt.u32.u64 %0, t; }" : "=r"(a) : "l"(p));
    return a;
}
#define SWZ(x) ((x) ^ (((x) >> 3) & 0x70))

#define CP16(dst, src) asm volatile("cp.async.ca.shared.global [%0], [%1], 16;" :: "r"(dst), "l"(src))
#define CP_COMMIT()    asm volatile("cp.async.commit_group;" ::: "memory")
#define CP_WAIT1()     asm volatile("cp.async.wait_group 1;" ::: "memory")

#define LDSM4(r0, r1, r2, r3, a) \
    asm volatile("ldmatrix.sync.aligned.m8n8.x4.shared.b16 {%0,%1,%2,%3}, [%4];" \
        : "=r"(r0), "=r"(r1), "=r"(r2), "=r"(r3) : "r"(a))
#define LDSM4T(r0, r1, r2, r3, a) \
    asm volatile("ldmatrix.sync.aligned.m8n8.x4.trans.shared.b16 {%0,%1,%2,%3}, [%4];" \
        : "=r"(r0), "=r"(r1), "=r"(r2), "=r"(r3) : "r"(a))

__device__ __forceinline__ void mma16816(float* c, const uint32_t a[4], uint32_t b0, uint32_t b1) {
    asm volatile("mma.sync.aligned.m16n8k16.row.col.f32.f16.f16.f32 "
        "{%0,%1,%2,%3},{%4,%5,%6,%7},{%8,%9},{%0,%1,%2,%3};"
        : "+f"(c[0]), "+f"(c[1]), "+f"(c[2]), "+f"(c[3])
        : "r"(a[0]), "r"(a[1]), "r"(a[2]), "r"(a[3]), "r"(b0), "r"(b1));
}
__device__ __forceinline__ void mma16816r(float* c, uint32_t a0, uint32_t a1, uint32_t a2, uint32_t a3,
                                          uint32_t b0, uint32_t b1) {
    asm volatile("mma.sync.aligned.m16n8k16.row.col.f32.f16.f16.f32 "
        "{%0,%1,%2,%3},{%4,%5,%6,%7},{%8,%9},{%0,%1,%2,%3};"
        : "+f"(c[0]), "+f"(c[1]), "+f"(c[2]), "+f"(c[3])
        : "r"(a0), "r"(a1), "r"(a2), "r"(a3), "r"(b0), "r"(b1));
}
__device__ __forceinline__ float ex2(float x) {
    float r; asm("ex2.approx.ftz.f32 %0, %1;" : "=f"(r) : "f"(x)); return r;
}
__device__ __forceinline__ uint32_t packh(float lo, float hi) {
    uint32_t r; asm("cvt.rn.f16x2.f32 %0, %2, %1;" : "=r"(r) : "f"(lo), "f"(hi)); return r;
}
__device__ __forceinline__ uint32_t ex2h2(uint32_t x) {
    uint32_t r; asm("ex2.approx.f16x2 %0, %1;" : "=r"(r) : "r"(x)); return r;
}
__device__ __forceinline__ uint32_t hadd2u(uint32_t a, uint32_t b) {
    uint32_t r; asm("add.rn.f16x2 %0, %1, %2;" : "=r"(r) : "r"(a), "r"(b)); return r;
}

__global__ void prep_kernel(const float* __restrict__ p, int n) {
    int i = blockIdx.x * blockDim.x + threadIdx.x;
    if (i < n) {
        float x = p[i];
        g_ph[i] = __float2half_rn(x);
        g_qh[i] = __float2half_rn(QSCALE * x);
    }
}

__global__ void __launch_bounds__(NTH, 1)
attn_kernel(const float* __restrict__ p, float* __restrict__ out, int N) {
    // [0,24K): 3-deep K ring; [24K,40K): Q (128 rows x 128B). Epilogue overlays all.
    __shared__ __align__(128) char sAll[40960];

    const int tid  = threadIdx.x;
    const int wid  = tid >> 5;
    const int lane = tid & 31;
    const int half = wid >> 2;          // key half [0,32) / [32,64)
    const int wrow = wid & 3;           // 32-row group
    const int NT   = N / TN;
    const uint32_t kbase[3] = { smem_u32(sAll), smem_u32(sAll + 8192), smem_u32(sAll + 16384) };
    const uint32_t qsm = smem_u32(sAll + 24576);

    const int c0 = tid, c1 = tid + NTH;
    const uint32_t sw0 = SWZ(c0 * 16), sw1 = SWZ(c1 * 16);
    const char* sqh = (const char*)g_qh;
    const char* sph = (const char*)g_ph;

    {   // stage Q (1024 chunks) + tile0 | tile1
        const size_t qoff = (size_t)blockIdx.x * 16384;
        #pragma unroll
        for (int r = 0; r < 4; r++) {
            int c = tid + r * NTH;
            CP16(qsm + SWZ(c * 16), sqh + qoff + c * 16);
        }
        CP16(kbase[0] + sw0, sph + c0 * 16);
        CP16(kbase[0] + sw1, sph + c1 * 16);
        CP_COMMIT();
        CP16(kbase[1] + sw0, sph + 8192 + c0 * 16);
        CP16(kbase[1] + sw1, sph + 8192 + c1 * 16);
        CP_COMMIT();
        CP_WAIT1();
        __syncthreads();
    }

    // Q fragments: 2 m-blocks x 4 k-blocks
    uint32_t qh[2][4][4];
    #pragma unroll
    for (int mb = 0; mb < 2; mb++) {
        const int qrow = wrow * 32 + mb * 16 + (lane & 7) + ((lane >> 3) & 1) * 8;
        const int qb16 = ((lane >> 4) & 1) * 16;
        #pragma unroll
        for (int kb = 0; kb < 4; kb++) {
            uint32_t off = SWZ((uint32_t)(qrow * 128 + kb * 32 + qb16));
            LDSM4(qh[mb][kb][0], qh[mb][kb][1], qh[mb][kb][2], qh[mb][kb][3], qsm + off);
        }
    }

    const uint32_t koffA = (uint32_t)((lane & 7) * 128 + (lane >> 3) * 16);
    const int nbase = half * 4;
    const int vrow  = (lane & 7) + ((lane >> 3) & 1) * 8;
    const uint32_t vb16 = ((lane >> 4) & 1) * 16;

    float O[2][32];
    #pragma unroll
    for (int mb = 0; mb < 2; mb++)
        #pragma unroll
        for (int i = 0; i < 32; i++) O[mb][i] = 0.f;
    float m[2][2], l[2][2];
    uint32_t Pc[2][2][4];

#define QK_BODY(qb_, S)                                                        \
    {                                                                          \
        _Pragma("unroll")                                                      \
        for (int i = 0; i < 32; i++) S[i] = 0.f;                               \
        _Pragma("unroll")                                                      \
        for (int c = 0; c < 2; c++) {                                          \
            _Pragma("unroll")                                                  \
            for (int j = 0; j < 4; j++) {                                      \
                uint32_t off = SWZ((uint32_t)((nbase + j) * 1024 + c * 64) + koffA); \
                uint32_t f0, f1, f2, f3;                                       \
                LDSM4(f0, f1, f2, f3, (qb_) + off);                            \
                _Pragma("unroll")                                              \
                for (int mb = 0; mb < 2; mb++) {                               \
                    mma16816(S + mb * 16 + j * 4, qh[mb][2 * c],     f0, f1);  \
                    mma16816(S + mb * 16 + j * 4, qh[mb][2 * c + 1], f2, f3);  \
                }                                                              \
            }                                                                  \
        }                                                                      \
    }

#define PV_BODY(pb_)                                                           \
    {                                                                          \
        _Pragma("unroll")                                                      \
        for (int kk = 0; kk < 2; kk++) {                                       \
            const int kbg = half * 2 + kk;                                     \
            _Pragma("unroll")                                                  \
            for (int c = 0; c < 4; c++) {                                      \
                uint32_t off = SWZ((uint32_t)((kbg * 16 + vrow) * 128 + c * 32 + vb16)); \
                uint32_t f0, f1, f2, f3;                                       \
                LDSM4T(f0, f1, f2, f3, (pb_) + off);                           \
                _Pragma("unroll")                                              \
                for (int mb = 0; mb < 2; mb++) {                               \
                    mma16816r(O[mb] + (2 * c) * 4,                             \
                        Pc[mb][0][2 * kk], Pc[mb][1][2 * kk],                  \
                        Pc[mb][0][2 * kk + 1], Pc[mb][1][2 * kk + 1], f0, f1); \
                    mma16816r(O[mb] + (2 * c + 1) * 4,                         \
                        Pc[mb][0][2 * kk], Pc[mb][1][2 * kk],                  \
                        Pc[mb][0][2 * kk + 1], Pc[mb][1][2 * kk + 1], f2, f3); \
                }                                                              \
            }                                                                  \
        }                                                                      \
    }

#define MIN_TREES(S, mc)                                                       \
    _Pragma("unroll")                                                          \
    for (int mb = 0; mb < 2; mb++) {                                           \
        const float* Sm = S + mb * 16;                                         \
        mc[mb][0] = fminf(fminf(fminf(Sm[0], Sm[1]),   fminf(Sm[4], Sm[5])),   \
                          fminf(fminf(Sm[8], Sm[9]),   fminf(Sm[12], Sm[13])));\
        mc[mb][1] = fminf(fminf(fminf(Sm[2], Sm[3]),   fminf(Sm[6], Sm[7])),   \
                          fminf(fminf(Sm[10], Sm[11]), fminf(Sm[14], Sm[15])));\
        mc[mb][0] = fminf(mc[mb][0], __shfl_xor_sync(0xffffffffu, mc[mb][0], 1)); \
        mc[mb][0] = fminf(mc[mb][0], __shfl_xor_sync(0xffffffffu, mc[mb][0], 2)); \
        mc[mb][1] = fminf(mc[mb][1], __shfl_xor_sync(0xffffffffu, mc[mb][1], 1)); \
        mc[mb][1] = fminf(mc[mb][1], __shfl_xor_sync(0xffffffffu, mc[mb][1], 2)); \
    }

#define P_GEN(S, mm, P)                                                        \
    _Pragma("unroll")                                                          \
    for (int mb = 0; mb < 2; mb++)                                             \
        _Pragma("unroll")                                                      \
        for (int j = 0; j < 4; j++) {                                          \
            P[mb][0][j] = ex2h2(packh(mm[mb][0] - S[mb*16 + j*4 + 0],          \
                                      mm[mb][0] - S[mb*16 + j*4 + 1]));        \
            P[mb][1][j] = ex2h2(packh(mm[mb][1] - S[mb*16 + j*4 + 2],          \
                                      mm[mb][1] - S[mb*16 + j*4 + 3]));        \
        }

#define L_ACC(P, l)                                                            \
    _Pragma("unroll")                                                          \
    for (int mb = 0; mb < 2; mb++)                                             \
        _Pragma("unroll")                                                      \
        for (int rp = 0; rp < 2; rp++) {                                       \
            uint32_t s_ = hadd2u(hadd2u(P[mb][rp][0], P[mb][rp][1]),           \
                                 hadd2u(P[mb][rp][2], P[mb][rp][3]));          \
            __half2 h_ = *(__half2*)&s_;                                       \
            l[mb][rp] += __low2float(h_) + __high2float(h_);                   \
        }

    {   // ---- prologue: QK(0), softmax(0) ----
        float S[32];
        QK_BODY(kbase[0], S);
        float mc[2][2];
        MIN_TREES(S, mc);
        #pragma unroll
        for (int mb = 0; mb < 2; mb++) { m[mb][0] = mc[mb][0]; m[mb][1] = mc[mb][1];
                                         l[mb][0] = 0.f;       l[mb][1] = 0.f; }
        P_GEN(S, m, Pc);
        L_ACC(Pc, l);
    }

    int ib0 = 0, ib1 = 1, ib2 = 2;
    for (int t = 0; t < NT - 1; t++) {
        if (t + 2 < NT) {
            const uint32_t nb_ = kbase[ib2];
            const char* s1 = sph + (size_t)(t + 2) * 8192;
            CP16(nb_ + sw0, s1 + c0 * 16);
            CP16(nb_ + sw1, s1 + c1 * 16);
        }
        CP_COMMIT();
        CP_WAIT1();
        __syncthreads();

        float S[32];
        QK_BODY(kbase[ib1], S);          // QK(t+1)

        float mc[2][2];
        MIN_TREES(S, mc);
        float mn[2][2];
        bool upd = false;
        #pragma unroll
        for (int mb = 0; mb < 2; mb++) {
            mn[mb][0] = fminf(m[mb][0], mc[mb][0]);
            mn[mb][1] = fminf(m[mb][1], mc[mb][1]);
            upd |= (mn[mb][0] < m[mb][0]) | (mn[mb][1] < m[mb][1]);
        }
        uint32_t Pn[2][2][4];
        P_GEN(S, mn, Pn);

        PV_BODY(kbase[ib0]);             // PV(t) at scale m(t) — overlaps softmax

        if (__any_sync(0xffffffffu, upd)) {
            #pragma unroll
            for (int mb = 0; mb < 2; mb++) {
                const float s0 = ex2(mn[mb][0] - m[mb][0]);
                const float s1 = ex2(mn[mb][1] - m[mb][1]);
                l[mb][0] *= s0;  l[mb][1] *= s1;
                #pragma unroll
                for (int j = 0; j < 8; j++) {
                    O[mb][j * 4 + 0] *= s0;  O[mb][j * 4 + 1] *= s0;
                    O[mb][j * 4 + 2] *= s1;  O[mb][j * 4 + 3] *= s1;
                }
            }
        }
        #pragma unroll
        for (int mb = 0; mb < 2; mb++) { m[mb][0] = mn[mb][0]; m[mb][1] = mn[mb][1]; }
        L_ACC(Pn, l);
        #pragma unroll
        for (int mb = 0; mb < 2; mb++)
            #pragma unroll
            for (int rp = 0; rp < 2; rp++)
                #pragma unroll
                for (int j = 0; j < 4; j++) Pc[mb][rp][j] = Pn[mb][rp][j];

        __syncthreads();
        int tmp = ib0; ib0 = ib1; ib1 = ib2; ib2 = tmp;
    }

    PV_BODY(kbase[ib0]);                 // PV(NT-1)

    // ---- merge the two key-half states (warp w <-> w^4) ----
    float* Ob = (float*)sAll;            // [128][66] = 33792 B
    float* Lb = Ob + 128 * 66;           // [128]
    float* Mx = Lb + 128;                // [8][32]

    #pragma unroll
    for (int mb = 0; mb < 2; mb++)
        #pragma unroll
        for (int rp = 0; rp < 2; rp++) {
            l[mb][rp] += __shfl_xor_sync(0xffffffffu, l[mb][rp], 1);
            l[mb][rp] += __shfl_xor_sync(0xffffffffu, l[mb][rp], 2);
        }

    const int rq = lane >> 2;
    __syncthreads();                     // PV(NT-1) smem reads done everywhere
    if ((lane & 3) == 0) {
        #pragma unroll
        for (int mb = 0; mb < 2; mb++) {
            Mx[wid * 32 + mb * 16 + rq]     = m[mb][0];
            Mx[wid * 32 + mb * 16 + 8 + rq] = m[mb][1];
        }
    }
    __syncthreads();
    #pragma unroll
    for (int mb = 0; mb < 2; mb++) {
        const float mp0 = Mx[(wid ^ 4) * 32 + mb * 16 + rq];
        const float mp1 = Mx[(wid ^ 4) * 32 + mb * 16 + 8 + rq];
        const float s0 = ex2(fminf(m[mb][0], mp0) - m[mb][0]);
        const float s1 = ex2(fminf(m[mb][1], mp1) - m[mb][1]);
        l[mb][0] *= s0;  l[mb][1] *= s1;
        #pragma unroll
        for (int j = 0; j < 8; j++) {
            O[mb][j * 4 + 0] *= s0;  O[mb][j * 4 + 1] *= s0;
            O[mb][j * 4 + 2] *= s1;  O[mb][j * 4 + 3] *= s1;
        }
    }
    const int cb = (lane & 3) * 2;
    if (half == 0) {
        #pragma unroll
        for (int mb = 0; mb < 2; mb++) {
            const int rb = wrow * 32 + mb * 16 + rq;
            #pragma unroll
            for (int j = 0; j < 8; j++) {
                Ob[rb * 66 + j * 8 + cb]           = O[mb][j * 4 + 0];
                Ob[rb * 66 + j * 8 + cb + 1]       = O[mb][j * 4 + 1];
                Ob[(rb + 8) * 66 + j * 8 + cb]     = O[mb][j * 4 + 2];
                Ob[(rb + 8) * 66 + j * 8 + cb + 1] = O[mb][j * 4 + 3];
            }
            if ((lane & 3) == 0) { Lb[rb] = l[mb][0]; Lb[rb + 8] = l[mb][1]; }
        }
    }
    __syncthreads();
    if (half == 1) {
        #pragma unroll
        for (int mb = 0; mb < 2; mb++) {
            const int rb = wrow * 32 + mb * 16 + rq;
            const float L0 = l[mb][0] + Lb[rb];
            const float L1 = l[mb][1] + Lb[rb + 8];
            const float i0 = 0.1f / L0, i1 = 0.1f / L1;
            const int r0 = blockIdx.x * TM + rb;
            const int r1 = r0 + 8;
            #pragma unroll
            for (int j = 0; j < 8; j++) {
                const int col = j * 8 + cb;
                float2 pv0 = *(const float2*)(p + (size_t)r0 * D_DIM + col);
                float2 pv1 = *(const float2*)(p + (size_t)r1 * D_DIM + col);
                float2 o0, o1;
                o0.x = 0.9f * pv0.x + (O[mb][j * 4 + 0] + Ob[rb * 66 + col])           * i0;
                o0.y = 0.9f * pv0.y + (O[mb][j * 4 + 1] + Ob[rb * 66 + col + 1])       * i0;
                o1.x = 0.9f * pv1.x + (O[mb][j * 4 + 2] + Ob[(rb + 8) * 66 + col])     * i1;
                o1.y = 0.9f * pv1.y + (O[mb][j * 4 + 3] + Ob[(rb + 8) * 66 + col + 1]) * i1;
                *(float2*)(out + (size_t)r0 * D_DIM + col) = o0;
                *(float2*)(out + (size_t)r1 * D_DIM + col) = o1;
            }
        }
    }
}

extern "C" void kernel_launch(void* const* d_in, const int* in_sizes, int n_in,
                              void* d_out, int out_size) {
    const float* p = (const float*)d_in[0];
    float* out = (float*)d_out;
    const int n = in_sizes[0];
    const int N = n / D_DIM;
    prep_kernel<<<(n + 255) / 256, 256>>>(p, n);
    attn_kernel<<<N / TM, NTH>>>(p, out, N);
}

// round 15
// speedup vs baseline: 1.1132x; 1.1132x over previous
#include <cuda_runtime.h>
#include <cuda_fp16.h>
#include <cstdint>

// out = 0.9*p + 0.1 * softmax(-4 p p^T) p    N=16384, D=64, fp32
// FA2 flash attention, single-pass f16 QK/PV, key-split 8 warps.
// Pipeline order per tile: QK(t+1) -> PV(t) -> softmax(t+1)  (PV issues ahead
// of the scalar chain so the tensor queue never drains). Ring-4 K buffers,
// one __syncthreads per tile.

#define D_DIM 64
#define TM    64
#define TN    64
#define NTH   256
#define PN    (16384*64)
#define QSCALE 5.770780163555854f   // 4*log2(e)

__device__ __half g_qh[PN];   // fp16(QSCALE*p)
__device__ __half g_ph[PN];   // fp16(p)  (K / V)

__device__ __forceinline__ uint32_t smem_u32(const void* p) {
    uint32_t a;
    asm("{ .reg .u64 t; cvta.to.shared.u64 t, %1; cvt.u32.u64 %0, t; }" : "=r"(a) : "l"(p));
    return a;
}
#define SWZ(x) ((x) ^ (((x) >> 3) & 0x70))

#define CP16(dst, src) asm volatile("cp.async.ca.shared.global [%0], [%1], 16;" :: "r"(dst), "l"(src))
#define CP_COMMIT()    asm volatile("cp.async.commit_group;" ::: "memory")
#define CP_WAIT1()     asm volatile("cp.async.wait_group 1;" ::: "memory")

#define LDSM4(r0, r1, r2, r3, a) \
    asm volatile("ldmatrix.sync.aligned.m8n8.x4.shared.b16 {%0,%1,%2,%3}, [%4];" \
        : "=r"(r0), "=r"(r1), "=r"(r2), "=r"(r3) : "r"(a))
#define LDSM4T(r0, r1, r2, r3, a) \
    asm volatile("ldmatrix.sync.aligned.m8n8.x4.trans.shared.b16 {%0,%1,%2,%3}, [%4];" \
        : "=r"(r0), "=r"(r1), "=r"(r2), "=r"(r3) : "r"(a))

__device__ __forceinline__ void mma16816(float* c, const uint32_t a[4], uint32_t b0, uint32_t b1) {
    asm volatile("mma.sync.aligned.m16n8k16.row.col.f32.f16.f16.f32 "
        "{%0,%1,%2,%3},{%4,%5,%6,%7},{%8,%9},{%0,%1,%2,%3};"
        : "+f"(c[0]), "+f"(c[1]), "+f"(c[2]), "+f"(c[3])
        : "r"(a[0]), "r"(a[1]), "r"(a[2]), "r"(a[3]), "r"(b0), "r"(b1));
}
__device__ __forceinline__ void mma16816r(float* c, uint32_t a0, uint32_t a1, uint32_t a2, uint32_t a3,
                                          uint32_t b0, uint32_t b1) {
    asm volatile("mma.sync.aligned.m16n8k16.row.col.f32.f16.f16.f32 "
        "{%0,%1,%2,%3},{%4,%5,%6,%7},{%8,%9},{%0,%1,%2,%3};"
        : "+f"(c[0]), "+f"(c[1]), "+f"(c[2]), "+f"(c[3])
        : "r"(a0), "r"(a1), "r"(a2), "r"(a3), "r"(b0), "r"(b1));
}
__device__ __forceinline__ float ex2(float x) {
    float r; asm("ex2.approx.ftz.f32 %0, %1;" : "=f"(r) : "f"(x)); return r;
}
__device__ __forceinline__ uint32_t packh(float lo, float hi) {
    uint32_t r; asm("cvt.rn.f16x2.f32 %0, %2, %1;" : "=r"(r) : "f"(lo), "f"(hi)); return r;
}
__device__ __forceinline__ uint32_t ex2h2(uint32_t x) {
    uint32_t r; asm("ex2.approx.f16x2 %0, %1;" : "=r"(r) : "r"(x)); return r;
}
__device__ __forceinline__ uint32_t hadd2u(uint32_t a, uint32_t b) {
    uint32_t r; asm("add.rn.f16x2 %0, %1, %2;" : "=r"(r) : "r"(a), "r"(b)); return r;
}

__global__ void prep_kernel(const float* __restrict__ p, int n) {
    int i = blockIdx.x * blockDim.x + threadIdx.x;
    if (i < n) {
        float x = p[i];
        g_ph[i] = __float2half_rn(x);
        g_qh[i] = __float2half_rn(QSCALE * x);
    }
}

__global__ void __launch_bounds__(NTH, 2)
attn_kernel(const float* __restrict__ p, float* __restrict__ out, int N) {
    // [0,32K): 4-deep K ring (t&3); [32K,40K): Q. Epilogue overlays the ring.
    __shared__ __align__(128) char sAll[40960];

    const int tid  = threadIdx.x;
    const int wid  = tid >> 5;
    const int lane = tid & 31;
    const int half = wid >> 2;
    const int wrow = wid & 3;
    const int NT   = N / TN;
    const uint32_t kr  = smem_u32(sAll);
    const uint32_t qsm = kr + 32768;
#define KB(t) (kr + (uint32_t)(((t) & 3) << 13))

    const int c0 = tid, c1 = tid + NTH;
    const uint32_t sw0 = SWZ(c0 * 16), sw1 = SWZ(c1 * 16);
    const char* sqh = (const char*)g_qh;
    const char* sph = (const char*)g_ph;

    {   // G0: Q + tile0 (buf0);  G1: tile1 (buf1)
        const size_t qoff = (size_t)blockIdx.x * 8192;
        CP16(qsm + sw0,   sqh + qoff + c0 * 16);
        CP16(qsm + sw1,   sqh + qoff + c1 * 16);
        CP16(KB(0) + sw0, sph + c0 * 16);
        CP16(KB(0) + sw1, sph + c1 * 16);
        CP_COMMIT();
        CP16(KB(1) + sw0, sph + 8192 + c0 * 16);
        CP16(KB(1) + sw1, sph + 8192 + c1 * 16);
        CP_COMMIT();
        CP_WAIT1();            // G0 done (Q + tile0)
        __syncthreads();
    }

    uint32_t qh[4][4];
    {
        const int qrow = wrow * 16 + (lane & 7) + ((lane >> 3) & 1) * 8;
        const int qb16 = ((lane >> 4) & 1) * 16;
        #pragma unroll
        for (int kb = 0; kb < 4; kb++) {
            uint32_t off = SWZ((uint32_t)(qrow * 128 + kb * 32 + qb16));
            LDSM4(qh[kb][0], qh[kb][1], qh[kb][2], qh[kb][3], qsm + off);
        }
    }

    const uint32_t koffA = (uint32_t)((lane & 7) * 128 + (lane >> 3) * 16);
    const int nbase = half * 4;
    const int vrow  = (lane & 7) + ((lane >> 3) & 1) * 8;
    const uint32_t vb16 = ((lane >> 4) & 1) * 16;

    float O[32];
    #pragma unroll
    for (int i = 0; i < 32; i++) O[i] = 0.f;
    float m0, m1, l0, l1;
    uint32_t Pc0[4], Pc1[4];

#define QK_BODY(qb_, S)                                                        \
    {                                                                          \
        _Pragma("unroll")                                                      \
        for (int i = 0; i < 16; i++) S[i] = 0.f;                               \
        _Pragma("unroll")                                                      \
        for (int c = 0; c < 2; c++) {                                          \
            _Pragma("unroll")                                                  \
            for (int j = 0; j < 4; j++) {                                      \
                uint32_t off = SWZ((uint32_t)((nbase + j) * 1024 + c * 64) + koffA); \
                uint32_t f0, f1, f2, f3;                                       \
                LDSM4(f0, f1, f2, f3, (qb_) + off);                            \
                mma16816(S + j * 4, qh[2 * c],     f0, f1);                    \
                mma16816(S + j * 4, qh[2 * c + 1], f2, f3);                    \
            }                                                                  \
        }                                                                      \
    }

#define PV_BODY(pb_)                                                           \
    {                                                                          \
        _Pragma("unroll")                                                      \
        for (int kk = 0; kk < 2; kk++) {                                       \
            const int kbg = half * 2 + kk;                                     \
            uint32_t pk0 = Pc0[2 * kk],     pk1 = Pc1[2 * kk];                 \
            uint32_t pk2 = Pc0[2 * kk + 1], pk3 = Pc1[2 * kk + 1];             \
            _Pragma("unroll")                                                  \
            for (int c = 0; c < 4; c++) {                                      \
                uint32_t off = SWZ((uint32_t)((kbg * 16 + vrow) * 128 + c * 32 + vb16)); \
                uint32_t f0, f1, f2, f3;                                       \
                LDSM4T(f0, f1, f2, f3, (pb_) + off);                           \
                mma16816r(O + (2 * c) * 4,     pk0, pk1, pk2, pk3, f0, f1);    \
                mma16816r(O + (2 * c + 1) * 4, pk0, pk1, pk2, pk3, f2, f3);    \
            }                                                                  \
        }                                                                      \
    }

#define MIN_TREES(S, mc0, mc1)                                                 \
    float mc0 = fminf(fminf(fminf(S[0], S[1]),   fminf(S[4], S[5])),           \
                      fminf(fminf(S[8], S[9]),   fminf(S[12], S[13])));        \
    float mc1 = fminf(fminf(fminf(S[2], S[3]),   fminf(S[6], S[7])),           \
                      fminf(fminf(S[10], S[11]), fminf(S[14], S[15])));        \
    mc0 = fminf(mc0, __shfl_xor_sync(0xffffffffu, mc0, 1));                    \
    mc0 = fminf(mc0, __shfl_xor_sync(0xffffffffu, mc0, 2));                    \
    mc1 = fminf(mc1, __shfl_xor_sync(0xffffffffu, mc1, 1));                    \
    mc1 = fminf(mc1, __shfl_xor_sync(0xffffffffu, mc1, 2));

    {   // ---- prologue: QK(0), softmax(0) ----
        float S[16];
        QK_BODY(KB(0), S);
        MIN_TREES(S, mc0, mc1);
        m0 = mc0;  m1 = mc1;
        #pragma unroll
        for (int j = 0; j < 4; j++) {
            Pc0[j] = ex2h2(packh(m0 - S[j * 4 + 0], m0 - S[j * 4 + 1]));
            Pc1[j] = ex2h2(packh(m1 - S[j * 4 + 2], m1 - S[j * 4 + 3]));
        }
        uint32_t s0 = hadd2u(hadd2u(Pc0[0], Pc0[1]), hadd2u(Pc0[2], Pc0[3]));
        uint32_t s1 = hadd2u(hadd2u(Pc1[0], Pc1[1]), hadd2u(Pc1[2], Pc1[3]));
        __half2 h0 = *(__half2*)&s0, h1 = *(__half2*)&s1;
        l0 = __low2float(h0) + __high2float(h0);
        l1 = __low2float(h1) + __high2float(h1);
    }

    for (int t = 0; t < NT - 1; t++) {
        // prefetch tile t+2 into KB(t+2); commit every iter so wait_group 1 is exact
        if (t + 2 < NT) {
            const uint32_t nb_ = KB(t + 2);
            const char* s1 = sph + (size_t)(t + 2) * 8192;
            CP16(nb_ + sw0, s1 + c0 * 16);
            CP16(nb_ + sw1, s1 + c1 * 16);
        }
        CP_COMMIT();
        CP_WAIT1();                 // tile t+1 landed
        __syncthreads();            // single barrier per tile (ring depth 4)

        float S[16];
        QK_BODY(KB(t + 1), S);      // QK(t+1)
        PV_BODY(KB(t));             // PV(t) issues BEFORE the scalar chain

        MIN_TREES(S, mc0, mc1);
        const float mn0 = fminf(m0, mc0), mn1 = fminf(m1, mc1);
        const bool upd = (mn0 < m0) | (mn1 < m1);
        if (__any_sync(0xffffffffu, upd)) {      // after PV: rebase O,l to m(t+1)
            const float sc0 = ex2(mn0 - m0), sc1 = ex2(mn1 - m1);
            l0 *= sc0;  l1 *= sc1;
            #pragma unroll
            for (int j = 0; j < 8; j++) {
                O[j * 4 + 0] *= sc0;  O[j * 4 + 1] *= sc0;
                O[j * 4 + 2] *= sc1;  O[j * 4 + 3] *= sc1;
            }
        }
        m0 = mn0;  m1 = mn1;
        #pragma unroll
        for (int j = 0; j < 4; j++) {
            Pc0[j] = ex2h2(packh(m0 - S[j * 4 + 0], m0 - S[j * 4 + 1]));
            Pc1[j] = ex2h2(packh(m1 - S[j * 4 + 2], m1 - S[j * 4 + 3]));
        }
        {
            uint32_t s0 = hadd2u(hadd2u(Pc0[0], Pc0[1]), hadd2u(Pc0[2], Pc0[3]));
            uint32_t s1 = hadd2u(hadd2u(Pc1[0], Pc1[1]), hadd2u(Pc1[2], Pc1[3]));
            __half2 h0 = *(__half2*)&s0, h1 = *(__half2*)&s1;
            l0 += __low2float(h0) + __high2float(h0);
            l1 += __low2float(h1) + __high2float(h1);
        }
    }

    PV_BODY(KB(NT - 1));            // PV(NT-1)

    // ---- merge the two key-half softmax states (warp w <-> w^4) ----
    float* Ob = (float*)sAll;                 // [64][66] overlay
    float* Lb = Ob + 64 * 66;
    float* Mx = Lb + 64;

    l0 += __shfl_xor_sync(0xffffffffu, l0, 1);
    l0 += __shfl_xor_sync(0xffffffffu, l0, 2);
    l1 += __shfl_xor_sync(0xffffffffu, l1, 1);
    l1 += __shfl_xor_sync(0xffffffffu, l1, 2);

    const int rq = lane >> 2;
    __syncthreads();
    if ((lane & 3) == 0) {
        Mx[wid * 16 + rq]     = m0;
        Mx[wid * 16 + 8 + rq] = m1;
    }
    __syncthreads();
    {
        const float mp0 = Mx[(wid ^ 4) * 16 + rq];
        const float mp1 = Mx[(wid ^ 4) * 16 + 8 + rq];
        const float s0 = ex2(fminf(m0, mp0) - m0);
        const float s1 = ex2(fminf(m1, mp1) - m1);
        l0 *= s0;  l1 *= s1;
        #pragma unroll
        for (int j = 0; j < 8; j++) {
            O[j * 4 + 0] *= s0;  O[j * 4 + 1] *= s0;
            O[j * 4 + 2] *= s1;  O[j * 4 + 3] *= s1;
        }
    }
    const int rb = wrow * 16 + rq;
    const int cb = (lane & 3) * 2;
    if (half == 0) {
        #pragma unroll
        for (int j = 0; j < 8; j++) {
            Ob[rb * 66 + j * 8 + cb]           = O[j * 4 + 0];
            Ob[rb * 66 + j * 8 + cb + 1]       = O[j * 4 + 1];
            Ob[(rb + 8) * 66 + j * 8 + cb]     = O[j * 4 + 2];
            Ob[(rb + 8) * 66 + j * 8 + cb + 1] = O[j * 4 + 3];
        }
        if ((lane & 3) == 0) { Lb[rb] = l0; Lb[rb + 8] = l1; }
    }
    __syncthreads();
    if (half == 1) {
        l0 += Lb[rb];
        l1 += Lb[rb + 8];
        const float i0 = 0.1f / l0, i1 = 0.1f / l1;
        const int r0 = blockIdx.x * TM + rb;
        const int r1 = r0 + 8;
        #pragma unroll
        for (int j = 0; j < 8; j++) {
            const int col = j * 8 + cb;
            float2 pv0 = *(const float2*)(p + (size_t)r0 * D_DIM + col);
            float2 pv1 = *(const float2*)(p + (size_t)r1 * D_DIM + col);
            float2 o0, o1;
            o0.x = 0.9f * pv0.x + (O[j * 4 + 0] + Ob[rb * 66 + col])           * i0;
            o0.y = 0.9f * pv0.y + (O[j * 4 + 1] + Ob[rb * 66 + col + 1])       * i0;
            o1.x = 0.9f * pv1.x + (O[j * 4 + 2] + Ob[(rb + 8) * 66 + col])     * i1;
            o1.y = 0.9f * pv1.y + (O[j * 4 + 3] + Ob[(rb + 8) * 66 + col + 1]) * i1;
            *(float2*)(out + (size_t)r0 * D_DIM + col) = o0;
            *(float2*)(out + (size_t)r1 * D_DIM + col) = o1;
        }
    }
}

extern "C" void kernel_launch(void* const* d_in, const int* in_sizes, int n_in,
                              void* d_out, int out_size) {
    const float* p = (const float*)d_in[0];
    float* out = (float*)d_out;
    const int n = in_sizes[0];
    const int N = n / D_DIM;
    prep_kernel<<<(n + 255) / 256, 256>>>(p, n);
    attn_kernel<<<N / TM, NTH>>>(p, out, N);
}